// round 14
// baseline (speedup 1.0000x reference)
#include <cuda_runtime.h>
#include <cstdint>

#define BB 4
#define NN 20000
#define EE 320000
#define INDIM 21
#define ED 64
#define H2 128
#define LL 3
#define BN_EPS 1e-5f
#define SCB 79              // scan blocks per batch (79*256 >= 20000)

// ---------------- scratch (device globals; no allocations) ----------------
__device__ __align__(16) float g_H[BB * NN * ED];    // current node embeddings
__device__ __align__(16) float g_A1[BB * NN * ED];   // gathered neighbor feature sums
__device__ __align__(16) float g_P[BB * NN * H2];    // pre-BN hidden activations
__device__ float g_deg[BB * NN];
__device__ float g_s[BB * NN];
__device__ float g_stats[LL * BB * 2 * H2];
__device__ float g_uv[LL * 2 * H2];
__device__ __align__(8) int2 g_ei32[BB * EE];
__device__ int g_rowptr[BB * NN];
__device__ int g_fill[BB * NN];
__device__ int g_csr[BB * EE];
__device__ int g_bsum[BB * SCB];
__device__ int g_is64;
// tf32 split weight fragments (hi0,hi1,lo0,lo1):
// W1_top [16 ntile][8 kt][32 lane]; W2 [8 nt][16 kt][32 lane]
__device__ __align__(16) uint4 g_W1f[LL * 16 * 8 * 32];
__device__ __align__(16) uint4 g_W2f[LL * 8 * 16 * 32];

__device__ __forceinline__ unsigned f2tf(float f) {
    unsigned u;
    asm("cvt.rna.tf32.f32 %0, %1;" : "=r"(u) : "f"(f));
    return u;
}

#define MMA_TF32(ACC, A0, A1r, A2, A3, B0, B1)                                   \
    asm volatile("mma.sync.aligned.m16n8k8.row.col.f32.tf32.tf32.f32 "           \
                 "{%0,%1,%2,%3}, {%4,%5,%6,%7}, {%8,%9}, {%0,%1,%2,%3};"         \
                 : "+f"(ACC[0]), "+f"(ACC[1]), "+f"(ACC[2]), "+f"(ACC[3])        \
                 : "r"(A0), "r"(A1r), "r"(A2), "r"(A3), "r"(B0), "r"(B1))

// ---------------- dtype detection for edge_index ----------------
__global__ void k_detect(const int* __restrict__ v) {
    __shared__ int nz[256];
    int t = threadIdx.x;
    nz[t] = v[2 * t + 1];
    __syncthreads();
    for (int s = 128; s > 0; s >>= 1) {
        if (t < s) nz[t] |= nz[t + s];
        __syncthreads();
    }
    if (t == 0) g_is64 = (nz[0] == 0) ? 1 : 0;
}

__global__ void k_zero_pass() {
    int i = blockIdx.x * blockDim.x + threadIdx.x;
    if (i < BB * NN) { g_deg[i] = 0.0f; g_s[i] = 0.0f; }
}

// ---------------- degree / edge-scalar scatter + edge-index repack ----------------
__global__ void k_degs(const void* __restrict__ ei, const float* __restrict__ eattr) {
    int gid = blockIdx.x * blockDim.x + threadIdx.x;
    if (gid >= BB * EE) return;
    int b = gid / EE, e = gid - b * EE;
    int src, dst;
    if (g_is64) {
        const long long* e64 = (const long long*)ei;
        src = (int)e64[(long long)b * 2 * EE + e];
        dst = (int)e64[(long long)b * 2 * EE + EE + e];
    } else {
        const int* e32 = (const int*)ei;
        src = e32[b * 2 * EE + e];
        dst = e32[b * 2 * EE + EE + e];
    }
    src = (src < 0) ? 0 : (src >= NN ? NN - 1 : src);
    dst = (dst < 0) ? 0 : (dst >= NN ? NN - 1 : dst);
    g_ei32[gid] = make_int2(src, dst);
    atomicAdd(&g_deg[b * NN + dst], 1.0f);
    atomicAdd(&g_s[b * NN + dst], eattr[gid]);
}

// ---------------- 3-phase parallel scan for CSR rowptr ----------------
__global__ void k_scan1() {
    __shared__ int sh[256];
    int blk = blockIdx.x;
    int batch = blk / SCB, loc = blk - batch * SCB;
    int node = loc * 256 + threadIdx.x;
    int d = (node < NN) ? (int)g_deg[batch * NN + node] : 0;
    sh[threadIdx.x] = d;
    __syncthreads();
    for (int s = 128; s > 0; s >>= 1) {
        if (threadIdx.x < s) sh[threadIdx.x] += sh[threadIdx.x + s];
        __syncthreads();
    }
    if (threadIdx.x == 0) g_bsum[blk] = sh[0];
}

__global__ void k_scan2() {
    __shared__ int sh[BB * SCB];
    int t = threadIdx.x;               // 512
    if (t < BB * SCB) sh[t] = g_bsum[t];
    __syncthreads();
    if (t < BB) {
        int off = 0;
        for (int i = 0; i < SCB; i++) {
            int v = sh[t * SCB + i];
            sh[t * SCB + i] = off;
            off += v;
        }
    }
    __syncthreads();
    if (t < BB * SCB) g_bsum[t] = sh[t];
}

__global__ void k_scan3() {
    __shared__ int sh[256];
    int blk = blockIdx.x;
    int batch = blk / SCB, loc = blk - batch * SCB;
    int node = loc * 256 + threadIdx.x;
    int t = threadIdx.x;
    int d = (node < NN) ? (int)g_deg[batch * NN + node] : 0;
    sh[t] = d;
    __syncthreads();
    for (int off = 1; off < 256; off <<= 1) {
        int y = (t >= off) ? sh[t - off] : 0;
        __syncthreads();
        sh[t] += y;
        __syncthreads();
    }
    if (node < NN) {
        int excl = sh[t] - d + g_bsum[blk];
        g_rowptr[batch * NN + node] = excl;
        g_fill[batch * NN + node] = excl;
    }
}

__global__ void k_fill() {
    int gid = blockIdx.x * blockDim.x + threadIdx.x;
    if (gid >= BB * EE) return;
    int b = gid / EE;
    int2 sd = g_ei32[gid];
    int pos = atomicAdd(&g_fill[b * NN + sd.y], 1);
    g_csr[b * EE + pos] = sd.x;
}

// ---------------- input embedding ----------------
__global__ void __launch_bounds__(256) k_embed(const float* __restrict__ x,
                                               const float* __restrict__ inW,
                                               const float* __restrict__ inb) {
    __shared__ __align__(16) float Wsh[INDIM * ED];
    __shared__ float xs[16][INDIM];
    int tid = threadIdx.x;
    for (int i = tid; i < INDIM * ED; i += 256) Wsh[i] = inW[i];
    int row0 = blockIdx.x * 16;
    for (int i = tid; i < 16 * INDIM; i += 256) {
        int r = i / INDIM, k = i - r * INDIM;
        xs[r][k] = x[(long long)(row0 + r) * INDIM + k];
    }
    __syncthreads();
    int r = tid >> 4;
    int c4 = tid & 15;
    float4 acc = *reinterpret_cast<const float4*>(&inb[c4 * 4]);
#pragma unroll
    for (int k = 0; k < INDIM; k++) {
        float xv = xs[r][k];
        float4 w = *reinterpret_cast<const float4*>(&Wsh[k * ED + c4 * 4]);
        acc.x += xv * w.x; acc.y += xv * w.y; acc.z += xv * w.z; acc.w += xv * w.w;
    }
    *reinterpret_cast<float4*>(&g_H[(long long)(row0 + r) * ED + c4 * 4]) = acc;
}

// ---------------- CSR gather ----------------
__global__ void __launch_bounds__(256) k_gather() {
    int gw = (blockIdx.x * blockDim.x + threadIdx.x) >> 5;
    if (gw >= BB * NN) return;
    int b = gw / NN, n = gw - b * NN;
    int lane = threadIdx.x & 31;
    int half = lane >> 4, c4 = lane & 15;
    int start = g_rowptr[b * NN + n];
    int end = start + (int)g_deg[b * NN + n];
    const int* csr = g_csr + b * EE;
    const float* Hb = g_H + (long long)b * NN * ED;
    float4 a0 = make_float4(0.f, 0.f, 0.f, 0.f);
    float4 a1 = make_float4(0.f, 0.f, 0.f, 0.f);
    int e = start + half;
    for (; e + 2 < end; e += 4) {
        int s0 = csr[e];
        int s1 = csr[e + 2];
        float4 v0 = *reinterpret_cast<const float4*>(&Hb[(long long)s0 * ED + c4 * 4]);
        float4 v1 = *reinterpret_cast<const float4*>(&Hb[(long long)s1 * ED + c4 * 4]);
        a0.x += v0.x; a0.y += v0.y; a0.z += v0.z; a0.w += v0.w;
        a1.x += v1.x; a1.y += v1.y; a1.z += v1.z; a1.w += v1.w;
    }
    if (e < end) {
        int s0 = csr[e];
        float4 v0 = *reinterpret_cast<const float4*>(&Hb[(long long)s0 * ED + c4 * 4]);
        a0.x += v0.x; a0.y += v0.y; a0.z += v0.z; a0.w += v0.w;
    }
    a0.x += a1.x; a0.y += a1.y; a0.z += a1.z; a0.w += a1.w;
    a0.x += __shfl_xor_sync(0xffffffffu, a0.x, 16);
    a0.y += __shfl_xor_sync(0xffffffffu, a0.y, 16);
    a0.z += __shfl_xor_sync(0xffffffffu, a0.z, 16);
    a0.w += __shfl_xor_sync(0xffffffffu, a0.w, 16);
    if (half == 0)
        *reinterpret_cast<float4*>(&g_A1[((long long)(b * NN + n)) * ED + c4 * 4]) = a0;
}

// ---------------- all-layer rank-1 terms u,v + zero BN stats ----------------
__global__ void k_uv_all(const float* __restrict__ edgeW, const float* __restrict__ edgeb,
                         const float* __restrict__ W1) {
    int l = blockIdx.x;
    int c = threadIdx.x;   // 128
    for (int i = c; i < BB * 2 * H2; i += 128) g_stats[l * BB * 2 * H2 + i] = 0.0f;
    float u = 0.f, v = 0.f;
#pragma unroll
    for (int k = 0; k < ED; k++) {
        float w1 = W1[((long long)l * H2 + ED + k) * H2 + c];
        u += edgeW[l * ED + k] * w1;
        v += edgeb[l * ED + k] * w1;
    }
    g_uv[l * 2 * H2 + c] = u;
    g_uv[l * 2 * H2 + H2 + c] = v;
}

// ---------------- weight fragment prepack (tf32 hi/lo split) ----------------
__global__ void k_wfrag(const float* __restrict__ W1, const float* __restrict__ W2) {
    int l = blockIdx.x;
    int tid = threadIdx.x;   // 256
    // W1_top [64,128] -> [16 ntile][8 kt][32 lane]
    for (int i = tid; i < 16 * 8 * 32; i += 256) {
        int ntile = i >> 8;
        int rem = i & 255;
        int kt = rem >> 5, lane = rem & 31;
        int k = kt * 8 + (lane & 3);
        int n = ntile * 8 + (lane >> 2);
        float b0 = W1[((long long)l * H2 + k) * H2 + n];
        float b1 = W1[((long long)l * H2 + k + 4) * H2 + n];
        unsigned h0 = f2tf(b0), h1 = f2tf(b1);
        unsigned l0 = f2tf(b0 - __uint_as_float(h0));
        unsigned l1 = f2tf(b1 - __uint_as_float(h1));
        g_W1f[l * 4096 + i] = make_uint4(h0, h1, l0, l1);
    }
    // W2 [128,64] -> [8 ntile][16 kt][32 lane]
    for (int i = tid; i < 8 * 16 * 32; i += 256) {
        int ntile = i >> 9;
        int rem = i & 511;
        int kt = rem >> 5, lane = rem & 31;
        int k = kt * 8 + (lane & 3);
        int n = ntile * 8 + (lane >> 2);
        float b0 = W2[((long long)l * H2 + k) * ED + n];
        float b1 = W2[((long long)l * H2 + k + 4) * ED + n];
        unsigned h0 = f2tf(b0), h1 = f2tf(b1);
        unsigned l0 = f2tf(b0 - __uint_as_float(h0));
        unsigned l1 = f2tf(b1 - __uint_as_float(h1));
        g_W2f[l * 4096 + i] = make_uint4(h0, h1, l0, l1);
    }
}

// ---------------- GEMM1 (3xTF32 MMA): P = A1 @ W1_top + b1 + s*u + deg*v, + BN stats ----------------
// 256 threads, 64 rows x 128 cols per block. Dynamic smem 86016 B.
__global__ void __launch_bounds__(256) k_gemm1(const float* __restrict__ b1, int l) {
    extern __shared__ __align__(16) unsigned char smemraw[];
    uint4*    bfr  = (uint4*)smemraw;                          // 65536
    float*    ash  = (float*)(smemraw + 65536);                // 64*68*4 = 17408 (f32)
    float*    uvb  = (float*)(smemraw + 65536 + 17408);        // 384 floats
    float*    srow = uvb + 384;                                // 128 floats (s:64, deg:64)
    float*    red  = srow + 128;                               // 256 floats

    int tid = threadIdx.x;
    int b = blockIdx.x;
    int n0 = blockIdx.y * 64;

    const uint4* wf = g_W1f + l * 4096;
    for (int i = tid; i < 4096; i += 256) bfr[i] = wf[i];
    // A tile (f32, padded 68); hi/lo split happens in registers
    for (int i = tid; i < 64 * 16; i += 256) {
        int r = i >> 4, c4 = i & 15;
        int gr = n0 + r; if (gr >= NN) gr = NN - 1;
        float4 v = reinterpret_cast<const float4*>(g_A1 + ((long long)(b * NN + gr)) * ED)[c4];
        *reinterpret_cast<float4*>(&ash[r * 68 + c4 * 4]) = v;
    }
    const float* uvl = g_uv + l * 2 * H2;
    for (int i = tid; i < 384; i += 256)
        uvb[i] = (i < 256) ? uvl[i] : b1[l * H2 + i - 256];
    for (int i = tid; i < 128; i += 256) {
        int r = i & 63;
        int gr = n0 + r; if (gr >= NN) gr = NN - 1;
        srow[i] = (i < 64) ? g_s[b * NN + gr] : g_deg[b * NN + gr];
    }
    if (tid < 256) red[tid] = 0.0f;
    __syncthreads();

    int w = tid >> 5, lane = tid & 31;
    int mrow = (w & 3) * 16;
    int nt0 = (w >> 2) * 8;

    float acc[8][4];
#pragma unroll
    for (int j = 0; j < 8; j++)
#pragma unroll
        for (int q = 0; q < 4; q++) acc[j][q] = 0.0f;

    int ar0 = (mrow + (lane >> 2)) * 68 + (lane & 3);
#pragma unroll
    for (int kt = 0; kt < 8; kt++) {
        float af0 = ash[ar0 + kt * 8];
        float af1 = ash[ar0 + 8 * 68 + kt * 8];
        float af2 = ash[ar0 + kt * 8 + 4];
        float af3 = ash[ar0 + 8 * 68 + kt * 8 + 4];
        unsigned ah0 = f2tf(af0), ah1 = f2tf(af1), ah2 = f2tf(af2), ah3 = f2tf(af3);
        unsigned al0 = f2tf(af0 - __uint_as_float(ah0));
        unsigned al1 = f2tf(af1 - __uint_as_float(ah1));
        unsigned al2 = f2tf(af2 - __uint_as_float(ah2));
        unsigned al3 = f2tf(af3 - __uint_as_float(ah3));
#pragma unroll
        for (int j = 0; j < 8; j++) {
            uint4 bb = bfr[((nt0 + j) * 8 + kt) * 32 + lane];
            MMA_TF32(acc[j], ah0, ah1, ah2, ah3, bb.x, bb.y);   // hi*hi
            MMA_TF32(acc[j], al0, al1, al2, al3, bb.x, bb.y);   // lo*hi
            MMA_TF32(acc[j], ah0, ah1, ah2, ah3, bb.z, bb.w);   // hi*lo
        }
    }

    // epilogue
    int ra = mrow + (lane >> 2);
    int rb = ra + 8;
    int ga = n0 + ra, gb = n0 + rb;
    bool va = ga < NN, vb = gb < NN;
    float sa = srow[ra], da = srow[64 + ra];
    float sb = srow[rb], db = srow[64 + rb];
#pragma unroll
    for (int j = 0; j < 8; j++) {
        int c0 = nt0 * 8 + j * 8 + 2 * (lane & 3);
        int c1 = c0 + 1;
        float u0 = uvb[c0], v0 = uvb[128 + c0], bb0 = uvb[256 + c0];
        float u1 = uvb[c1], v1 = uvb[128 + c1], bb1 = uvb[256 + c1];
        float f0 = acc[j][0] + bb0 + sa * u0 + da * v0;
        float f1 = acc[j][1] + bb1 + sa * u1 + da * v1;
        float f2 = acc[j][2] + bb0 + sb * u0 + db * v0;
        float f3 = acc[j][3] + bb1 + sb * u1 + db * v1;
        if (va) *reinterpret_cast<float2*>(&g_P[((long long)(b * NN + ga)) * H2 + c0]) = make_float2(f0, f1);
        if (vb) *reinterpret_cast<float2*>(&g_P[((long long)(b * NN + gb)) * H2 + c0]) = make_float2(f2, f3);
        float t0 = (va ? f0 : 0.f) + (vb ? f2 : 0.f);
        float t1 = (va ? f1 : 0.f) + (vb ? f3 : 0.f);
        float q0 = (va ? f0 * f0 : 0.f) + (vb ? f2 * f2 : 0.f);
        float q1 = (va ? f1 * f1 : 0.f) + (vb ? f3 * f3 : 0.f);
#pragma unroll
        for (int s = 4; s < 32; s <<= 1) {
            t0 += __shfl_xor_sync(0xffffffffu, t0, s);
            t1 += __shfl_xor_sync(0xffffffffu, t1, s);
            q0 += __shfl_xor_sync(0xffffffffu, q0, s);
            q1 += __shfl_xor_sync(0xffffffffu, q1, s);
        }
        if ((lane >> 2) == 0) {
            atomicAdd(&red[c0], t0);
            atomicAdd(&red[c1], t1);
            atomicAdd(&red[128 + c0], q0);
            atomicAdd(&red[128 + c1], q1);
        }
    }
    __syncthreads();
    float* st = g_stats + (l * BB + b) * 2 * H2;
    if (tid < 256) atomicAdd(&st[tid], red[tid]);
}

// ---------------- GEMM2 (3xTF32 MMA): h' = relu(BN(P)) @ W2 + b2 ----------------
// 256 threads, 64 rows x 64 cols per block. Dynamic smem 100608 B.
__global__ void __launch_bounds__(256) k_gemm2(const float* __restrict__ b2,
                                               const float* __restrict__ gamma,
                                               const float* __restrict__ beta,
                                               float* __restrict__ out, int l, int writeOut) {
    extern __shared__ __align__(16) unsigned char smemraw[];
    uint4*    bfr  = (uint4*)smemraw;                          // 65536
    float*    qsh  = (float*)(smemraw + 65536);                // 64*132*4 = 33792 (f32)
    float*    scls = (float*)(smemraw + 65536 + 33792);        // 256 floats (scl,shf)
    float*    b2s  = scls + 256;                               // 64 floats

    int tid = threadIdx.x;
    int b = blockIdx.x;
    int n0 = blockIdx.y * 64;

    const uint4* wf = g_W2f + l * 4096;
    for (int i = tid; i < 4096; i += 256) bfr[i] = wf[i];
    if (tid < 128) {
        const float* st = g_stats + (l * BB + b) * 2 * H2;
        float sum = st[tid];
        float sq  = st[H2 + tid];
        float m = sum / (float)NN;
        float var = sq / (float)NN - m * m;
        float rstd = rsqrtf(var + BN_EPS);
        float scl = rstd * gamma[l * H2 + tid];
        scls[tid] = scl;
        scls[128 + tid] = beta[l * H2 + tid] - m * scl;
    }
    if (tid < 64) b2s[tid] = b2[l * ED + tid];
    __syncthreads();

    // build q = relu(P*scl+shf) in f32, padded 132
    for (int i = tid; i < 64 * 32; i += 256) {
        int r = i >> 5, c4 = i & 31;
        int gr = n0 + r; if (gr >= NN) gr = NN - 1;
        float4 p = reinterpret_cast<const float4*>(g_P + ((long long)(b * NN + gr)) * H2)[c4];
        int c = c4 * 4;
        float4 q;
        q.x = fmaxf(p.x * scls[c] + scls[128 + c], 0.f);
        q.y = fmaxf(p.y * scls[c + 1] + scls[128 + c + 1], 0.f);
        q.z = fmaxf(p.z * scls[c + 2] + scls[128 + c + 2], 0.f);
        q.w = fmaxf(p.w * scls[c + 3] + scls[128 + c + 3], 0.f);
        *reinterpret_cast<float4*>(&qsh[r * 132 + c]) = q;
    }
    __syncthreads();

    int w = tid >> 5, lane = tid & 31;
    int mrow = (w & 3) * 16;
    int nt0 = (w >> 2) * 4;

    float acc[4][4];
#pragma unroll
    for (int j = 0; j < 4; j++)
#pragma unroll
        for (int q = 0; q < 4; q++) acc[j][q] = 0.0f;

    int ar0 = (mrow + (lane >> 2)) * 132 + (lane & 3);
#pragma unroll
    for (int kt = 0; kt < 16; kt++) {
        float af0 = qsh[ar0 + kt * 8];
        float af1 = qsh[ar0 + 8 * 132 + kt * 8];
        float af2 = qsh[ar0 + kt * 8 + 4];
        float af3 = qsh[ar0 + 8 * 132 + kt * 8 + 4];
        unsigned ah0 = f2tf(af0), ah1 = f2tf(af1), ah2 = f2tf(af2), ah3 = f2tf(af3);
        unsigned al0 = f2tf(af0 - __uint_as_float(ah0));
        unsigned al1 = f2tf(af1 - __uint_as_float(ah1));
        unsigned al2 = f2tf(af2 - __uint_as_float(ah2));
        unsigned al3 = f2tf(af3 - __uint_as_float(ah3));
#pragma unroll
        for (int j = 0; j < 4; j++) {
            uint4 bb = bfr[((nt0 + j) * 16 + kt) * 32 + lane];
            MMA_TF32(acc[j], ah0, ah1, ah2, ah3, bb.x, bb.y);   // hi*hi
            MMA_TF32(acc[j], al0, al1, al2, al3, bb.x, bb.y);   // lo*hi
            MMA_TF32(acc[j], ah0, ah1, ah2, ah3, bb.z, bb.w);   // hi*lo
        }
    }

    int ra = mrow + (lane >> 2);
    int ga = n0 + ra, gb = ga + 8;
    bool va = ga < NN, vb = gb < NN;
#pragma unroll
    for (int j = 0; j < 4; j++) {
        int c0 = nt0 * 8 + j * 8 + 2 * (lane & 3);
        float f0 = acc[j][0] + b2s[c0];
        float f1 = acc[j][1] + b2s[c0 + 1];
        float f2 = acc[j][2] + b2s[c0];
        float f3 = acc[j][3] + b2s[c0 + 1];
        if (writeOut) {
            if (va) *reinterpret_cast<float2*>(&out[((long long)(b * NN + ga)) * ED + c0]) = make_float2(f0, f1);
            if (vb) *reinterpret_cast<float2*>(&out[((long long)(b * NN + gb)) * ED + c0]) = make_float2(f2, f3);
        } else {
            f0 = fmaxf(f0, 0.f); f1 = fmaxf(f1, 0.f);
            f2 = fmaxf(f2, 0.f); f3 = fmaxf(f3, 0.f);
            if (va) *reinterpret_cast<float2*>(&g_H[((long long)(b * NN + ga)) * ED + c0]) = make_float2(f0, f1);
            if (vb) *reinterpret_cast<float2*>(&g_H[((long long)(b * NN + gb)) * ED + c0]) = make_float2(f2, f3);
        }
    }
}

// ---------------- launcher ----------------
extern "C" void kernel_launch(void* const* d_in, const int* in_sizes, int n_in,
                              void* d_out, int out_size) {
    const float*     x      = (const float*)d_in[0];
    const void*      ei     = (const void*)d_in[1];
    const float*     eattr  = (const float*)d_in[2];
    const float*     inW    = (const float*)d_in[3];
    const float*     inb    = (const float*)d_in[4];
    const float*     edgeW  = (const float*)d_in[5];
    const float*     edgeb  = (const float*)d_in[6];
    const float*     W1     = (const float*)d_in[7];
    const float*     b1     = (const float*)d_in[8];
    const float*     gamma  = (const float*)d_in[9];
    const float*     beta   = (const float*)d_in[10];
    const float*     W2     = (const float*)d_in[11];
    const float*     b2     = (const float*)d_in[12];
    float* out = (float*)d_out;

    static bool attrs_set = false;
    if (!attrs_set) {
        cudaFuncSetAttribute(k_gemm1, cudaFuncAttributeMaxDynamicSharedMemorySize, 86016);
        cudaFuncSetAttribute(k_gemm2, cudaFuncAttributeMaxDynamicSharedMemorySize, 100608);
        attrs_set = true;
    }

    k_detect<<<1, 256>>>((const int*)ei);
    k_zero_pass<<<(BB * NN + 255) / 256, 256>>>();
    k_uv_all<<<LL, 128>>>(edgeW, edgeb, W1);
    k_wfrag<<<LL, 256>>>(W1, W2);
    k_degs<<<(BB * EE + 255) / 256, 256>>>(ei, eattr);
    k_scan1<<<BB * SCB, 256>>>();
    k_scan2<<<1, 512>>>();
    k_scan3<<<BB * SCB, 256>>>();
    k_fill<<<(BB * EE + 255) / 256, 256>>>();
    k_embed<<<BB * NN / 16, 256>>>(x, inW, inb);

    const int GY = (NN + 63) / 64;   // 313
    for (int l = 0; l < LL; l++) {
        k_gather<<<(BB * NN * 32 + 255) / 256, 256>>>();
        k_gemm1<<<dim3(BB, GY), 256, 86016>>>(b1, l);
        k_gemm2<<<dim3(BB, GY), 256, 100608>>>(b2, gamma, beta, out, l, (l == LL - 1) ? 1 : 0);
    }
}

// round 15
// speedup vs baseline: 1.3242x; 1.3242x over previous
#include <cuda_runtime.h>
#include <cstdint>

#define BB 4
#define NN 20000
#define EE 320000
#define INDIM 21
#define ED 64
#define H2 128
#define LL 3
#define BN_EPS 1e-5f
#define SCB 79              // scan blocks per batch (79*256 >= 20000)

// ---------------- scratch (device globals; no allocations) ----------------
__device__ __align__(16) float g_H[BB * NN * ED];    // current node embeddings
__device__ __align__(16) float g_A1[BB * NN * ED];   // gathered neighbor feature sums
__device__ __align__(16) float g_P[BB * NN * H2];    // pre-BN hidden activations
__device__ float g_deg[BB * NN];
__device__ float g_s[BB * NN];
__device__ float g_stats[LL * BB * 2 * H2];
__device__ float g_uv[LL * 2 * H2];
__device__ __align__(8) int2 g_ei32[BB * EE];
__device__ int g_rowptr[BB * NN];
__device__ int g_fill[BB * NN];
__device__ int g_csr[BB * EE];
__device__ int g_bsum[BB * SCB];
__device__ int g_is64;

// ---------------- dtype detection for edge_index ----------------
__global__ void k_detect(const int* __restrict__ v) {
    __shared__ int nz[256];
    int t = threadIdx.x;
    nz[t] = v[2 * t + 1];
    __syncthreads();
    for (int s = 128; s > 0; s >>= 1) {
        if (t < s) nz[t] |= nz[t + s];
        __syncthreads();
    }
    if (t == 0) g_is64 = (nz[0] == 0) ? 1 : 0;
}

__global__ void k_zero_pass() {
    int i = blockIdx.x * blockDim.x + threadIdx.x;
    if (i < BB * NN) { g_deg[i] = 0.0f; g_s[i] = 0.0f; }
}

// ---------------- degree / edge-scalar scatter + edge-index repack ----------------
__global__ void k_degs(const void* __restrict__ ei, const float* __restrict__ eattr) {
    int gid = blockIdx.x * blockDim.x + threadIdx.x;
    if (gid >= BB * EE) return;
    int b = gid / EE, e = gid - b * EE;
    int src, dst;
    if (g_is64) {
        const long long* e64 = (const long long*)ei;
        src = (int)e64[(long long)b * 2 * EE + e];
        dst = (int)e64[(long long)b * 2 * EE + EE + e];
    } else {
        const int* e32 = (const int*)ei;
        src = e32[b * 2 * EE + e];
        dst = e32[b * 2 * EE + EE + e];
    }
    src = (src < 0) ? 0 : (src >= NN ? NN - 1 : src);
    dst = (dst < 0) ? 0 : (dst >= NN ? NN - 1 : dst);
    g_ei32[gid] = make_int2(src, dst);
    atomicAdd(&g_deg[b * NN + dst], 1.0f);
    atomicAdd(&g_s[b * NN + dst], eattr[gid]);
}

// ---------------- 3-phase parallel scan for CSR rowptr ----------------
__global__ void k_scan1() {
    __shared__ int sh[256];
    int blk = blockIdx.x;
    int batch = blk / SCB, loc = blk - batch * SCB;
    int node = loc * 256 + threadIdx.x;
    int d = (node < NN) ? (int)g_deg[batch * NN + node] : 0;
    sh[threadIdx.x] = d;
    __syncthreads();
    for (int s = 128; s > 0; s >>= 1) {
        if (threadIdx.x < s) sh[threadIdx.x] += sh[threadIdx.x + s];
        __syncthreads();
    }
    if (threadIdx.x == 0) g_bsum[blk] = sh[0];
}

__global__ void k_scan2() {
    __shared__ int sh[BB * SCB];
    int t = threadIdx.x;               // 512
    if (t < BB * SCB) sh[t] = g_bsum[t];
    __syncthreads();
    if (t < BB) {
        int off = 0;
        for (int i = 0; i < SCB; i++) {
            int v = sh[t * SCB + i];
            sh[t * SCB + i] = off;
            off += v;
        }
    }
    __syncthreads();
    if (t < BB * SCB) g_bsum[t] = sh[t];
}

__global__ void k_scan3() {
    __shared__ int sh[256];
    int blk = blockIdx.x;
    int batch = blk / SCB, loc = blk - batch * SCB;
    int node = loc * 256 + threadIdx.x;
    int t = threadIdx.x;
    int d = (node < NN) ? (int)g_deg[batch * NN + node] : 0;
    sh[t] = d;
    __syncthreads();
    for (int off = 1; off < 256; off <<= 1) {
        int y = (t >= off) ? sh[t - off] : 0;
        __syncthreads();
        sh[t] += y;
        __syncthreads();
    }
    if (node < NN) {
        int excl = sh[t] - d + g_bsum[blk];
        g_rowptr[batch * NN + node] = excl;
        g_fill[batch * NN + node] = excl;
    }
}

__global__ void k_fill() {
    int gid = blockIdx.x * blockDim.x + threadIdx.x;
    if (gid >= BB * EE) return;
    int b = gid / EE;
    int2 sd = g_ei32[gid];
    int pos = atomicAdd(&g_fill[b * NN + sd.y], 1);
    g_csr[b * EE + pos] = sd.x;
}

// ---------------- input embedding ----------------
__global__ void __launch_bounds__(256) k_embed(const float* __restrict__ x,
                                               const float* __restrict__ inW,
                                               const float* __restrict__ inb) {
    __shared__ __align__(16) float Wsh[INDIM * ED];
    __shared__ float xs[16][INDIM];
    int tid = threadIdx.x;
    for (int i = tid; i < INDIM * ED; i += 256) Wsh[i] = inW[i];
    int row0 = blockIdx.x * 16;
    for (int i = tid; i < 16 * INDIM; i += 256) {
        int r = i / INDIM, k = i - r * INDIM;
        xs[r][k] = x[(long long)(row0 + r) * INDIM + k];
    }
    __syncthreads();
    int r = tid >> 4;
    int c4 = tid & 15;
    float4 acc = *reinterpret_cast<const float4*>(&inb[c4 * 4]);
#pragma unroll
    for (int k = 0; k < INDIM; k++) {
        float xv = xs[r][k];
        float4 w = *reinterpret_cast<const float4*>(&Wsh[k * ED + c4 * 4]);
        acc.x += xv * w.x; acc.y += xv * w.y; acc.z += xv * w.z; acc.w += xv * w.w;
    }
    *reinterpret_cast<float4*>(&g_H[(long long)(row0 + r) * ED + c4 * 4]) = acc;
}

// ---------------- CSR gather: A1[n] = sum over in-edges of h[src] ----------------
// One warp per node; lanes split in 2 halves; each half keeps 4 edges in flight
// (MLP=4/thread) to cover L2 latency.
__global__ void __launch_bounds__(256) k_gather() {
    int gw = (blockIdx.x * blockDim.x + threadIdx.x) >> 5;
    if (gw >= BB * NN) return;
    int b = gw / NN, n = gw - b * NN;
    int lane = threadIdx.x & 31;
    int half = lane >> 4, c4 = lane & 15;
    int start = g_rowptr[b * NN + n];
    int end = start + (int)g_deg[b * NN + n];
    const int* csr = g_csr + b * EE;
    const float* Hb = g_H + (long long)b * NN * ED;
    float4 a0 = make_float4(0.f, 0.f, 0.f, 0.f);
    float4 a1 = make_float4(0.f, 0.f, 0.f, 0.f);
    float4 a2 = make_float4(0.f, 0.f, 0.f, 0.f);
    float4 a3 = make_float4(0.f, 0.f, 0.f, 0.f);
    int e = start + half;
    for (; e + 6 < end; e += 8) {
        int s0 = csr[e];
        int s1 = csr[e + 2];
        int s2 = csr[e + 4];
        int s3 = csr[e + 6];
        float4 v0 = *reinterpret_cast<const float4*>(&Hb[(long long)s0 * ED + c4 * 4]);
        float4 v1 = *reinterpret_cast<const float4*>(&Hb[(long long)s1 * ED + c4 * 4]);
        float4 v2 = *reinterpret_cast<const float4*>(&Hb[(long long)s2 * ED + c4 * 4]);
        float4 v3 = *reinterpret_cast<const float4*>(&Hb[(long long)s3 * ED + c4 * 4]);
        a0.x += v0.x; a0.y += v0.y; a0.z += v0.z; a0.w += v0.w;
        a1.x += v1.x; a1.y += v1.y; a1.z += v1.z; a1.w += v1.w;
        a2.x += v2.x; a2.y += v2.y; a2.z += v2.z; a2.w += v2.w;
        a3.x += v3.x; a3.y += v3.y; a3.z += v3.z; a3.w += v3.w;
    }
    for (; e < end; e += 2) {
        int s0 = csr[e];
        float4 v0 = *reinterpret_cast<const float4*>(&Hb[(long long)s0 * ED + c4 * 4]);
        a0.x += v0.x; a0.y += v0.y; a0.z += v0.z; a0.w += v0.w;
    }
    a0.x += a1.x + a2.x + a3.x;
    a0.y += a1.y + a2.y + a3.y;
    a0.z += a1.z + a2.z + a3.z;
    a0.w += a1.w + a2.w + a3.w;
    a0.x += __shfl_xor_sync(0xffffffffu, a0.x, 16);
    a0.y += __shfl_xor_sync(0xffffffffu, a0.y, 16);
    a0.z += __shfl_xor_sync(0xffffffffu, a0.z, 16);
    a0.w += __shfl_xor_sync(0xffffffffu, a0.w, 16);
    if (half == 0)
        *reinterpret_cast<float4*>(&g_A1[((long long)(b * NN + n)) * ED + c4 * 4]) = a0;
}

// ---------------- all-layer rank-1 terms u,v + zero BN stats ----------------
__global__ void k_uv_all(const float* __restrict__ edgeW, const float* __restrict__ edgeb,
                         const float* __restrict__ W1) {
    int l = blockIdx.x;
    int c = threadIdx.x;   // 128
    for (int i = c; i < BB * 2 * H2; i += 128) g_stats[l * BB * 2 * H2 + i] = 0.0f;
    float u = 0.f, v = 0.f;
#pragma unroll
    for (int k = 0; k < ED; k++) {
        float w1 = W1[((long long)l * H2 + ED + k) * H2 + c];
        u += edgeW[l * ED + k] * w1;
        v += edgeb[l * ED + k] * w1;
    }
    g_uv[l * 2 * H2 + c] = u;
    g_uv[l * 2 * H2 + H2 + c] = v;
}

// ---------------- GEMM1 (fp32): P = A1 @ W1_top + b1 + s*u + deg*v, + BN stats ----------------
__global__ void __launch_bounds__(128) k_gemm1(const float* __restrict__ W1,
                                               const float* __restrict__ b1, int l) {
    __shared__ __align__(16) float Wsh[ED * H2];   // 32 KB, [k][c]
    __shared__ __align__(16) float ash[32 * ED];   // 8 KB, 32 rows of A1
    __shared__ float red[4][2 * H2];               // 4 KB
    int tid = threadIdx.x;               // 128
    int b = blockIdx.x;
    int n0 = blockIdx.y * 32;

    for (int i = tid; i < ED * H2; i += 128) Wsh[i] = W1[(long long)l * H2 * H2 + i];
    {
        const float4* A1b = reinterpret_cast<const float4*>(g_A1 + ((long long)(b * NN + n0)) * ED);
        float4* a4 = reinterpret_cast<float4*>(ash);
        for (int i = tid; i < 32 * ED / 4; i += 128) a4[i] = A1b[i];
    }
    __syncthreads();

    int ry = tid >> 5;    // warp id: 4 groups of 8 rows
    int cx = tid & 31;    // 4 consecutive channels per thread

    const float* uvl = g_uv + l * 2 * H2;
    float uc[4], vc[4], b1c[4];
#pragma unroll
    for (int j = 0; j < 4; j++) {
        int c = cx * 4 + j;
        uc[j] = uvl[c];
        vc[j] = uvl[H2 + c];
        b1c[j] = b1[l * H2 + c];
    }
    float acc[8][4];
#pragma unroll
    for (int i = 0; i < 8; i++) {
        int n = n0 + ry * 8 + i;
        float sv = g_s[b * NN + n];
        float dv = g_deg[b * NN + n];
#pragma unroll
        for (int j = 0; j < 4; j++) acc[i][j] = b1c[j] + sv * uc[j] + dv * vc[j];
    }

#pragma unroll 4
    for (int k = 0; k < ED; k++) {
        float4 w = *reinterpret_cast<const float4*>(&Wsh[k * H2 + cx * 4]);
#pragma unroll
        for (int i = 0; i < 8; i++) {
            float a = ash[(ry * 8 + i) * ED + k];
            acc[i][0] += a * w.x; acc[i][1] += a * w.y;
            acc[i][2] += a * w.z; acc[i][3] += a * w.w;
        }
    }

    float sc[4] = {0.f, 0.f, 0.f, 0.f};
    float sq[4] = {0.f, 0.f, 0.f, 0.f};
#pragma unroll
    for (int i = 0; i < 8; i++) {
        int n = n0 + ry * 8 + i;
        float4 o = make_float4(acc[i][0], acc[i][1], acc[i][2], acc[i][3]);
        *reinterpret_cast<float4*>(&g_P[((long long)(b * NN + n)) * H2 + cx * 4]) = o;
#pragma unroll
        for (int j = 0; j < 4; j++) { sc[j] += acc[i][j]; sq[j] += acc[i][j] * acc[i][j]; }
    }
#pragma unroll
    for (int j = 0; j < 4; j++) {
        red[ry][cx * 4 + j] = sc[j];
        red[ry][H2 + cx * 4 + j] = sq[j];
    }
    __syncthreads();
    float* st = g_stats + (l * BB + b) * 2 * H2;
    for (int i = tid; i < 2 * H2; i += 128) {
        float t = red[0][i] + red[1][i] + red[2][i] + red[3][i];
        atomicAdd(&st[i], t);
    }
}

// ---------------- GEMM2 (fp32): h' = relu(BN(P)) @ W2 + b2, BN coeffs in-block ----------------
__global__ void __launch_bounds__(128) k_gemm2(const float* __restrict__ W2,
                                               const float* __restrict__ b2,
                                               const float* __restrict__ gamma,
                                               const float* __restrict__ beta,
                                               float* __restrict__ out, int l, int writeOut) {
    __shared__ __align__(16) float Wsh[H2 * ED];   // 32 KB, [k][c]
    __shared__ __align__(16) float qsh[32 * H2];   // 16 KB
    int tid = threadIdx.x;             // 128
    int b = blockIdx.x;
    int n0 = blockIdx.y * 32;

    for (int i = tid; i < H2 * ED; i += 128) Wsh[i] = W2[(long long)l * H2 * ED + i];

    const float* st = g_stats + (l * BB + b) * 2 * H2;
    float sum = st[tid];
    float sq  = st[H2 + tid];
    float m = sum / (float)NN;
    float var = sq / (float)NN - m * m;
    float rstd = rsqrtf(var + BN_EPS);
    float scl = rstd * gamma[l * H2 + tid];
    float shf = beta[l * H2 + tid] - m * scl;

    const float* Pb = g_P + ((long long)(b * NN + n0)) * H2;
#pragma unroll 4
    for (int r = 0; r < 32; r++) {
        float p = Pb[r * H2 + tid];
        float q = p * scl + shf;
        qsh[r * H2 + tid] = q > 0.f ? q : 0.f;
    }
    __syncthreads();

    int ry = tid >> 4;   // 8 row-groups of 4 rows
    int cx = tid & 15;   // 4 consecutive output channels per thread
    float acc[4][4];
#pragma unroll
    for (int i = 0; i < 4; i++)
#pragma unroll
        for (int j = 0; j < 4; j++) acc[i][j] = b2[l * ED + cx * 4 + j];

#pragma unroll 8
    for (int k = 0; k < H2; k++) {
        float4 w = *reinterpret_cast<const float4*>(&Wsh[k * ED + cx * 4]);
        float a0 = qsh[(ry * 4 + 0) * H2 + k];
        float a1 = qsh[(ry * 4 + 1) * H2 + k];
        float a2 = qsh[(ry * 4 + 2) * H2 + k];
        float a3 = qsh[(ry * 4 + 3) * H2 + k];
        acc[0][0] += a0 * w.x; acc[0][1] += a0 * w.y; acc[0][2] += a0 * w.z; acc[0][3] += a0 * w.w;
        acc[1][0] += a1 * w.x; acc[1][1] += a1 * w.y; acc[1][2] += a1 * w.z; acc[1][3] += a1 * w.w;
        acc[2][0] += a2 * w.x; acc[2][1] += a2 * w.y; acc[2][2] += a2 * w.z; acc[2][3] += a2 * w.w;
        acc[3][0] += a3 * w.x; acc[3][1] += a3 * w.y; acc[3][2] += a3 * w.z; acc[3][3] += a3 * w.w;
    }

#pragma unroll
    for (int i = 0; i < 4; i++) {
        int n = n0 + ry * 4 + i;
        float4 o;
        if (writeOut) {
            o = make_float4(acc[i][0], acc[i][1], acc[i][2], acc[i][3]);
            *reinterpret_cast<float4*>(&out[((long long)(b * NN + n)) * ED + cx * 4]) = o;
        } else {
            o = make_float4(acc[i][0] > 0.f ? acc[i][0] : 0.f,
                            acc[i][1] > 0.f ? acc[i][1] : 0.f,
                            acc[i][2] > 0.f ? acc[i][2] : 0.f,
                            acc[i][3] > 0.f ? acc[i][3] : 0.f);
            *reinterpret_cast<float4*>(&g_H[((long long)(b * NN + n)) * ED + cx * 4]) = o;
        }
    }
}

// ---------------- launcher ----------------
extern "C" void kernel_launch(void* const* d_in, const int* in_sizes, int n_in,
                              void* d_out, int out_size) {
    const float*     x      = (const float*)d_in[0];
    const void*      ei     = (const void*)d_in[1];
    const float*     eattr  = (const float*)d_in[2];
    const float*     inW    = (const float*)d_in[3];
    const float*     inb    = (const float*)d_in[4];
    const float*     edgeW  = (const float*)d_in[5];
    const float*     edgeb  = (const float*)d_in[6];
    const float*     W1     = (const float*)d_in[7];
    const float*     b1     = (const float*)d_in[8];
    const float*     gamma  = (const float*)d_in[9];
    const float*     beta   = (const float*)d_in[10];
    const float*     W2     = (const float*)d_in[11];
    const float*     b2     = (const float*)d_in[12];
    float* out = (float*)d_out;

    k_detect<<<1, 256>>>((const int*)ei);
    k_zero_pass<<<(BB * NN + 255) / 256, 256>>>();
    k_uv_all<<<LL, 128>>>(edgeW, edgeb, W1);
    k_degs<<<(BB * EE + 255) / 256, 256>>>(ei, eattr);
    k_scan1<<<BB * SCB, 256>>>();
    k_scan2<<<1, 512>>>();
    k_scan3<<<BB * SCB, 256>>>();
    k_fill<<<(BB * EE + 255) / 256, 256>>>();
    k_embed<<<BB * NN / 16, 256>>>(x, inW, inb);

    for (int l = 0; l < LL; l++) {
        k_gather<<<(BB * NN * 32 + 255) / 256, 256>>>();
        k_gemm1<<<dim3(BB, NN / 32), 128>>>(W1, b1, l);
        k_gemm2<<<dim3(BB, NN / 32), 128>>>(W2, b2, gamma, beta, out, l, (l == LL - 1) ? 1 : 0);
    }
}